// round 2
// baseline (speedup 1.0000x reference)
#include <cuda_runtime.h>
#include <math.h>

#define BB 4
#define HH 64
#define WW 64
#define CC 128
#define PP 4096
#define SPLITS 8

// ---------------- static scratch (no cudaMalloc allowed) ----------------
__device__ float g_x[BB * PP * 2];          // per-pixel (mean, max) over C
__device__ float g_xfq[BB * PP * 20];       // padded 18-dim patch vectors (queries / raw patches)
__device__ float g_M[BB * PP];              // L2 norm of each patch
__device__ float g_wn[BB * PP * 20];        // compacted normalized keys (valid p only)
__device__ float g_xfe[BB * PP * 12];       // compacted value vectors (channel 0 taps, 9 padded to 12)
__device__ int   g_valid[PP];
__device__ int   g_need[PP];
__device__ int   g_counts[2];               // [0]=n_valid, [1]=n_need
__device__ float g_pl[BB * SPLITS * PP];    // split-K partial denominators
__device__ float g_pa[(size_t)BB * SPLITS * PP * 12]; // split-K partial numerators
__device__ float g_tmp9[BB * PP * 9];       // attn @ values (channel-0 taps), per needed row
__device__ float g_sig[BB * PP];            // sigmoid(gate conv)
__device__ float g_y0[BB * PP];             // transpose-conv channel 0 at masked pixels

// ---------------- K1: channel mean/max -> g_x ----------------
__global__ void k1_meanmax(const float* __restrict__ inp) {
    int warp = (blockIdx.x * blockDim.x + threadIdx.x) >> 5;
    int lane = threadIdx.x & 31;
    if (warp >= BB * PP) return;
    const float4* base = (const float4*)(inp + (size_t)warp * CC);
    float4 v = base[lane];
    float s = (v.x + v.y) + (v.z + v.w);
    float m = fmaxf(fmaxf(v.x, v.y), fmaxf(v.z, v.w));
    #pragma unroll
    for (int o = 16; o; o >>= 1) {
        s += __shfl_xor_sync(0xffffffffu, s, o);
        m = fmaxf(m, __shfl_xor_sync(0xffffffffu, m, o));
    }
    if (lane == 0) {
        g_x[warp * 2 + 0] = s * (1.0f / 128.0f);
        g_x[warp * 2 + 1] = m;
    }
}

// ---------------- K2a: mm flags + needed-row flags + deterministic compaction ----------------
__global__ void k2a_compact(const float* __restrict__ mask) {
    int t = threadIdx.x;              // 256 threads, 16 pixels each
    int lane = t & 31, wid = t >> 5;
    unsigned fv = 0, fn = 0;
    int cv = 0, cn = 0;
    int base_p = t * 16;
    for (int i = 0; i < 16; i++) {
        int p = base_p + i, y = p >> 6, x = p & 63;
        int allone = 1, anyz = 0;
        #pragma unroll
        for (int dy = -1; dy <= 1; dy++)
            #pragma unroll
            for (int dx = -1; dx <= 1; dx++) {
                int yy = y + dy, xx = x + dx;
                if (yy < 0 || yy >= HH || xx < 0 || xx >= WW) {
                    allone = 0;            // zero-padded mask patch -> mean < 1
                } else {
                    float mv = mask[(yy << 6) + xx];
                    if (mv < 0.5f) { allone = 0; anyz = 1; }
                }
            }
        if (allone) { fv |= (1u << i); cv++; }
        if (anyz)   { fn |= (1u << i); cn++; }
    }
    // warp inclusive scan
    int iv = cv, inn = cn;
    #pragma unroll
    for (int o = 1; o < 32; o <<= 1) {
        int a = __shfl_up_sync(0xffffffffu, iv, o);
        int b = __shfl_up_sync(0xffffffffu, inn, o);
        if (lane >= o) { iv += a; inn += b; }
    }
    __shared__ int wv[8], wn_[8];
    if (lane == 31) { wv[wid] = iv; wn_[wid] = inn; }
    __syncthreads();
    int bv = 0, bn = 0;
    for (int i = 0; i < wid; i++) { bv += wv[i]; bn += wn_[i]; }
    int offv = bv + iv - cv;
    int offn = bn + inn - cn;
    for (int i = 0; i < 16; i++) {
        if (fv & (1u << i)) g_valid[offv++] = base_p + i;
        if (fn & (1u << i)) g_need[offn++]  = base_p + i;
    }
    if (t == 255) { g_counts[0] = bv + iv; g_counts[1] = bn + inn; }
}

// ---------------- K2b: build padded patch vectors + norms ----------------
__global__ void k2b_patches() {
    int idx = blockIdx.x * blockDim.x + threadIdx.x;   // BB*PP
    if (idx >= BB * PP) return;
    int p = idx & 4095, y = p >> 6, x = p & 63;
    int b = idx >> 12;
    float v[18];
    float ss = 0.f;
    int j = 0;
    #pragma unroll
    for (int kh = 0; kh < 3; kh++)
        #pragma unroll
        for (int kw = 0; kw < 3; kw++) {
            int yy = y + kh - 1, xx = x + kw - 1;
            float a = 0.f, c1 = 0.f;
            if (yy >= 0 && yy < HH && xx >= 0 && xx < WW) {
                int q = (b << 12) + (yy << 6) + xx;
                a  = g_x[q * 2 + 0];
                c1 = g_x[q * 2 + 1];
            }
            v[j] = a; v[j + 1] = c1;
            ss += a * a + c1 * c1;
            j += 2;
        }
    float* dst = g_xfq + (size_t)idx * 20;
    #pragma unroll
    for (int i = 0; i < 18; i++) dst[i] = v[i];
    dst[18] = 0.f; dst[19] = 0.f;
    g_M[idx] = sqrtf(ss);
}

// ---------------- K2c: compact normalized keys + values ----------------
__global__ void k2c_keys() {
    int idx = blockIdx.x * blockDim.x + threadIdx.x;
    if (idx >= BB * PP) return;
    int b = idx >> 12, v = idx & 4095;
    int nvalid = g_counts[0];
    if (v >= nvalid) return;
    int p = g_valid[v];
    int srcI = (b << 12) + p;
    float M = g_M[srcI];
    float rn = 1.f / fmaxf(M, 1e-4f);
    const float* src = g_xfq + (size_t)srcI * 20;
    float* dw = g_wn  + (size_t)((b << 12) + v) * 20;
    float* de = g_xfe + (size_t)((b << 12) + v) * 12;
    #pragma unroll
    for (int i = 0; i < 18; i++) dw[i] = src[i] * rn;
    dw[18] = 0.f; dw[19] = 0.f;
    #pragma unroll
    for (int k = 0; k < 9; k++) de[k] = src[2 * k];   // (kh,kw,c): c=0 taps at even indices
    de[9] = 0.f; de[10] = 0.f; de[11] = 0.f;
}

// ---------------- Kgate: 7x7x2 gate conv + sigmoid ----------------
__global__ void kgate(const float* __restrict__ convw) {
    __shared__ float sw[98];
    if (threadIdx.x < 98) sw[threadIdx.x] = convw[threadIdx.x];
    __syncthreads();
    int idx = blockIdx.x * blockDim.x + threadIdx.x;
    if (idx >= BB * PP) return;
    int b = idx >> 12, p = idx & 4095, y = p >> 6, x = p & 63;
    float g = 0.f;
    #pragma unroll
    for (int u = 0; u < 7; u++) {
        int yy = y + u - 3;
        if (yy < 0 || yy >= HH) continue;
        #pragma unroll
        for (int v = 0; v < 7; v++) {
            int xx = x + v - 3;
            if (xx < 0 || xx >= WW) continue;
            int q = (b << 12) + (yy << 6) + xx;
            g += g_x[q * 2 + 0] * sw[(u * 7 + v) * 2 + 0]
               + g_x[q * 2 + 1] * sw[(u * 7 + v) * 2 + 1];
        }
    }
    g_sig[idx] = 1.f / (1.f + __expf(-g));
}

// ---------------- K3: fused score GEMM + streaming softmax + value GEMM (split-K) ----------------
__global__ void __launch_bounds__(256) k3_attn() {
    __shared__ float swn[256 * 20];
    __shared__ float sxe[256 * 12];
    int nneed = g_counts[1];
    if ((int)(blockIdx.x * 256) >= nneed) return;
    int nvalid = g_counts[0];
    int b = blockIdx.y, s = blockIdx.z;
    int chunk = (nvalid + SPLITS - 1) / SPLITS;
    int v0 = s * chunk;
    int v1 = min(v0 + chunk, nvalid);
    int r = blockIdx.x * 256 + threadIdx.x;
    bool active = r < nneed;
    float4 q0, q1, q2, q3, q4;
    float M = 0.f;
    if (active) {
        int n = g_need[r];
        const float4* q = (const float4*)(g_xfq + (size_t)((b << 12) + n) * 20);
        q0 = q[0]; q1 = q[1]; q2 = q[2]; q3 = q[3]; q4 = q[4];
        M = g_M[(b << 12) + n];
    } else {
        q0 = q1 = q2 = q3 = q4 = make_float4(0.f, 0.f, 0.f, 0.f);
    }
    float l = 0.f;
    float4 a0 = make_float4(0.f, 0.f, 0.f, 0.f), a1 = a0, a2 = a0;
    int t = threadIdx.x;
    for (int base = v0; base < v1; base += 256) {
        int cnt = min(256, v1 - base);
        if (t < cnt) {
            const float4* src = (const float4*)(g_wn + (size_t)((b << 12) + base + t) * 20);
            float4* dst = (float4*)(swn + t * 20);
            dst[0] = src[0]; dst[1] = src[1]; dst[2] = src[2]; dst[3] = src[3]; dst[4] = src[4];
            const float4* s2 = (const float4*)(g_xfe + (size_t)((b << 12) + base + t) * 12);
            float4* d2 = (float4*)(sxe + t * 12);
            d2[0] = s2[0]; d2[1] = s2[1]; d2[2] = s2[2];
        }
        __syncthreads();
        if (active) {
            for (int j = 0; j < cnt; j++) {
                const float4* w = (const float4*)(swn + j * 20);
                float4 w0 = w[0], w1 = w[1], w2 = w[2], w3 = w[3], w4 = w[4];
                float sa = q0.x * w0.x + q1.x * w1.x + q2.x * w2.x + q3.x * w3.x + q4.x * w4.x;
                float sb = q0.y * w0.y + q1.y * w1.y + q2.y * w2.y + q3.y * w3.y + q4.y * w4.y;
                float sc = q0.z * w0.z + q1.z * w1.z + q2.z * w2.z + q3.z * w3.z + q4.z * w4.z;
                float sd = q0.w * w0.w + q1.w * w1.w + q2.w * w2.w + q3.w * w3.w + q4.w * w4.w;
                float sv = (sa + sb) + (sc + sd);
                float e = __expf(sv - M);   // sv <= M always (||wn||<=1), no rescale needed
                l += e;
                const float4* xe = (const float4*)(sxe + j * 12);
                float4 x0 = xe[0], x1 = xe[1], x2 = xe[2];
                a0.x = fmaf(e, x0.x, a0.x); a0.y = fmaf(e, x0.y, a0.y);
                a0.z = fmaf(e, x0.z, a0.z); a0.w = fmaf(e, x0.w, a0.w);
                a1.x = fmaf(e, x1.x, a1.x); a1.y = fmaf(e, x1.y, a1.y);
                a1.z = fmaf(e, x1.z, a1.z); a1.w = fmaf(e, x1.w, a1.w);
                a2.x = fmaf(e, x2.x, a2.x); a2.y = fmaf(e, x2.y, a2.y);
                a2.z = fmaf(e, x2.z, a2.z); a2.w = fmaf(e, x2.w, a2.w);
            }
        }
        __syncthreads();
    }
    if (active) {
        int basei = ((b * SPLITS + s) << 12) + r;
        g_pl[basei] = l;
        float4* pa = (float4*)(g_pa + (size_t)basei * 12);
        pa[0] = a0; pa[1] = a1; pa[2] = a2;
    }
}

// ---------------- K3r: deterministic split-K reduce + normalize ----------------
__global__ void k3r_reduce() {
    int idx = blockIdx.x * blockDim.x + threadIdx.x;
    if (idx >= BB * PP) return;
    int b = idx >> 12, r = idx & 4095;
    if (r >= g_counts[1]) return;
    int n = g_need[r];
    int nvalid = g_counts[0];
    // masked keys contribute exp(0 - M) each to the softmax denominator
    float l = (float)(PP - nvalid) * __expf(-g_M[(b << 12) + n]);
    float acc[12];
    #pragma unroll
    for (int k = 0; k < 12; k++) acc[k] = 0.f;
    #pragma unroll
    for (int s = 0; s < SPLITS; s++) {
        int basei = ((b * SPLITS + s) << 12) + r;
        l += g_pl[basei];
        const float4* pa = (const float4*)(g_pa + (size_t)basei * 12);
        float4 p0 = pa[0], p1 = pa[1], p2 = pa[2];
        acc[0] += p0.x; acc[1] += p0.y; acc[2]  += p0.z; acc[3]  += p0.w;
        acc[4] += p1.x; acc[5] += p1.y; acc[6]  += p1.z; acc[7]  += p1.w;
        acc[8] += p2.x; acc[9] += p2.y; acc[10] += p2.z; acc[11] += p2.w;
    }
    float rl = 1.f / l;
    float* dst = g_tmp9 + (size_t)((b << 12) + n) * 9;
    #pragma unroll
    for (int k = 0; k < 9; k++) dst[k] = acc[k] * rl;
}

// ---------------- K4: transpose-conv gather (channel 0) at masked pixels ----------------
__global__ void k4_y0(const float* __restrict__ mask) {
    int idx = blockIdx.x * blockDim.x + threadIdx.x;
    if (idx >= BB * PP) return;
    int b = idx >> 12, p = idx & 4095, y = p >> 6, x = p & 63;
    float y0 = 0.f;
    if (mask[p] < 0.5f) {
        float acc = 0.f;
        #pragma unroll
        for (int kh = 0; kh < 3; kh++)
            #pragma unroll
            for (int kw = 0; kw < 3; kw++) {
                int ny = y - (kh - 1), nx = x - (kw - 1);
                if (ny >= 0 && ny < HH && nx >= 0 && nx < WW)
                    acc += g_tmp9[(size_t)((b << 12) + (ny << 6) + nx) * 9 + kh * 3 + kw];
            }
        y0 = acc * 0.25f;
    }
    g_y0[idx] = y0;
}

// ---------------- K5: final elementwise ----------------
__global__ void k5_final(const float* __restrict__ inp, const float* __restrict__ mask,
                         const float* __restrict__ bias, float* __restrict__ out) {
    int i4 = blockIdx.x * blockDim.x + threadIdx.x;   // float4 index
    if (i4 >= BB * PP * (CC / 4)) return;
    int bp = i4 >> 5;         // CC/4 = 32 float4 per pixel
    int c4 = i4 & 31;
    int p = bp & 4095;
    float w = 1.0f - mask[p];
    float yb = g_y0[bp];
    float sg = g_sig[bp];
    float4 iv = ((const float4*)inp)[i4];
    float4 bv = ((const float4*)bias)[(p << 5) + c4];
    float4 o;
    o.x = sg * (iv.x + (yb + bv.x) * w);
    o.y = sg * (iv.y + (yb + bv.y) * w);
    o.z = sg * (iv.z + (yb + bv.z) * w);
    o.w = sg * (iv.w + (yb + bv.w) * w);
    ((float4*)out)[i4] = o;
}

// ---------------- launch ----------------
extern "C" void kernel_launch(void* const* d_in, const int* in_sizes, int n_in,
                              void* d_out, int out_size) {
    const float* inp   = (const float*)d_in[0];
    const float* mask  = (const float*)d_in[1];
    const float* bias  = (const float*)d_in[2];
    const float* convw = (const float*)d_in[3];
    float* out = (float*)d_out;

    k1_meanmax<<<(BB * PP) / 8, 256>>>(inp);
    k2a_compact<<<1, 256>>>(mask);
    k2b_patches<<<(BB * PP) / 256, 256>>>();
    k2c_keys<<<(BB * PP) / 256, 256>>>();
    kgate<<<(BB * PP) / 256, 256>>>(convw);
    dim3 g3((PP + 255) / 256, BB, SPLITS);
    k3_attn<<<g3, 256>>>();
    k3r_reduce<<<(BB * PP) / 256, 256>>>();
    k4_y0<<<(BB * PP) / 256, 256>>>(mask);
    k5_final<<<(BB * PP * (CC / 4)) / 256, 256>>>(inp, mask, bias, out);
}

// round 3
// speedup vs baseline: 1.3620x; 1.3620x over previous
#include <cuda_runtime.h>
#include <math.h>

#define BB 4
#define HH 64
#define WW 64
#define CC 128
#define PP 4096
#define SPLITS 16

// ---------------- static scratch (no cudaMalloc allowed) ----------------
__device__ float g_x[BB * PP * 2];          // per-pixel (mean, max) over C
__device__ float g_xfq[BB * PP * 20];       // padded 18-dim patch vectors (queries / raw patches)
__device__ float g_M[BB * PP];              // L2 norm of each patch
__device__ float g_wn[BB * PP * 20];        // compacted normalized keys (valid p only)
__device__ float g_xfe[BB * PP * 12];       // compacted value vectors (channel 0 taps, 9 padded to 12)
__device__ int   g_valid[PP];
__device__ int   g_need[PP];
__device__ int   g_counts[2];               // [0]=n_valid, [1]=n_need
__device__ float g_pl[BB * SPLITS * PP];    // split-K partial denominators
__device__ float g_pa[(size_t)BB * SPLITS * PP * 12]; // split-K partial numerators
__device__ float g_tmp9[BB * PP * 9];       // attn @ values (channel-0 taps), per needed row

// ---------------- KA: channel mean/max (blocks 0..2047) + mask compaction (block 2048) ----------------
__global__ void kA(const float* __restrict__ inp, const float* __restrict__ mask) {
    __shared__ int wv[8], wn_[8];
    if (blockIdx.x == 2048) {
        // --- compaction: mm flags + needed-row flags, deterministic order ---
        int t = threadIdx.x;              // 256 threads, 16 pixels each
        int lane = t & 31, wid = t >> 5;
        unsigned fv = 0, fn = 0;
        int cv = 0, cn = 0;
        int base_p = t * 16;
        for (int i = 0; i < 16; i++) {
            int p = base_p + i, y = p >> 6, x = p & 63;
            int allone = 1, anyz = 0;
            #pragma unroll
            for (int dy = -1; dy <= 1; dy++)
                #pragma unroll
                for (int dx = -1; dx <= 1; dx++) {
                    int yy = y + dy, xx = x + dx;
                    if (yy < 0 || yy >= HH || xx < 0 || xx >= WW) {
                        allone = 0;        // zero-padded mask patch -> mean < 1
                    } else {
                        float mv = mask[(yy << 6) + xx];
                        if (mv < 0.5f) { allone = 0; anyz = 1; }
                    }
                }
            if (allone) { fv |= (1u << i); cv++; }
            if (anyz)   { fn |= (1u << i); cn++; }
        }
        int iv = cv, inn = cn;
        #pragma unroll
        for (int o = 1; o < 32; o <<= 1) {
            int a = __shfl_up_sync(0xffffffffu, iv, o);
            int b = __shfl_up_sync(0xffffffffu, inn, o);
            if (lane >= o) { iv += a; inn += b; }
        }
        if (lane == 31) { wv[wid] = iv; wn_[wid] = inn; }
        __syncthreads();
        int bv = 0, bn = 0;
        for (int i = 0; i < wid; i++) { bv += wv[i]; bn += wn_[i]; }
        int offv = bv + iv - cv;
        int offn = bn + inn - cn;
        for (int i = 0; i < 16; i++) {
            if (fv & (1u << i)) g_valid[offv++] = base_p + i;
            if (fn & (1u << i)) g_need[offn++]  = base_p + i;
        }
        if (t == 255) { g_counts[0] = bv + iv; g_counts[1] = bn + inn; }
        return;
    }
    // --- mean/max: one warp per pixel ---
    int warp = blockIdx.x * 8 + (threadIdx.x >> 5);
    int lane = threadIdx.x & 31;
    const float4* base = (const float4*)(inp + (size_t)warp * CC);
    float4 v = base[lane];
    float s = (v.x + v.y) + (v.z + v.w);
    float m = fmaxf(fmaxf(v.x, v.y), fmaxf(v.z, v.w));
    #pragma unroll
    for (int o = 16; o; o >>= 1) {
        s += __shfl_xor_sync(0xffffffffu, s, o);
        m = fmaxf(m, __shfl_xor_sync(0xffffffffu, m, o));
    }
    if (lane == 0) {
        g_x[warp * 2 + 0] = s * (1.0f / 128.0f);
        g_x[warp * 2 + 1] = m;
    }
}

// ---------------- KB: build padded patch vectors + norms ----------------
__global__ void kB_patches() {
    int idx = blockIdx.x * blockDim.x + threadIdx.x;   // BB*PP
    if (idx >= BB * PP) return;
    int p = idx & 4095, y = p >> 6, x = p & 63;
    int b = idx >> 12;
    float v[18];
    float ss = 0.f;
    int j = 0;
    #pragma unroll
    for (int kh = 0; kh < 3; kh++)
        #pragma unroll
        for (int kw = 0; kw < 3; kw++) {
            int yy = y + kh - 1, xx = x + kw - 1;
            float a = 0.f, c1 = 0.f;
            if (yy >= 0 && yy < HH && xx >= 0 && xx < WW) {
                int q = (b << 12) + (yy << 6) + xx;
                a  = g_x[q * 2 + 0];
                c1 = g_x[q * 2 + 1];
            }
            v[j] = a; v[j + 1] = c1;
            ss += a * a + c1 * c1;
            j += 2;
        }
    float* dst = g_xfq + (size_t)idx * 20;
    #pragma unroll
    for (int i = 0; i < 18; i++) dst[i] = v[i];
    dst[18] = 0.f; dst[19] = 0.f;
    g_M[idx] = sqrtf(ss);
}

// ---------------- KC: compact normalized keys + values, 8 threads per key ----------------
__global__ void kC_keys() {
    int tid = blockIdx.x * blockDim.x + threadIdx.x;   // BB*PP*8
    int key = tid >> 3, w = tid & 7;
    int b = key >> 12, v = key & 4095;
    if (v >= g_counts[0]) return;
    int p = g_valid[v];
    int srcI = (b << 12) + p;
    const float4* src = (const float4*)(g_xfq + (size_t)srcI * 20);
    if (w < 5) {
        float rn = 1.f / fmaxf(g_M[srcI], 1e-4f);
        float4 sv = src[w];                 // pad words 18,19 are 0 -> stay 0
        float4 o = make_float4(sv.x * rn, sv.y * rn, sv.z * rn, sv.w * rn);
        ((float4*)(g_wn + (size_t)((b << 12) + v) * 20))[w] = o;
    } else {
        int k = w - 5;                      // value word 0..2; de[i]=src[2i] (c=0 taps)
        float4 o;
        if (k < 2) {
            float4 s0 = src[2 * k], s1 = src[2 * k + 1];
            o = make_float4(s0.x, s0.z, s1.x, s1.z);
        } else {
            float4 s0 = src[4];
            o = make_float4(s0.x, 0.f, 0.f, 0.f);
        }
        ((float4*)(g_xfe + (size_t)((b << 12) + v) * 12))[k] = o;
    }
}

// ---------------- KD: fused score GEMM + streaming softmax + value GEMM (split-K, 2 rows/thread) ----------------
__global__ void __launch_bounds__(256) kD_attn() {
    __shared__ float swn[256 * 20];
    __shared__ float sxe[256 * 12];
    int nneed = g_counts[1];
    if ((int)(blockIdx.x * 512) >= nneed) return;
    int nvalid = g_counts[0];
    int b = blockIdx.y, s = blockIdx.z;
    int chunk = (nvalid + SPLITS - 1) / SPLITS;
    int v0 = s * chunk;
    int v1 = min(v0 + chunk, nvalid);
    int t = threadIdx.x;
    int r0 = blockIdx.x * 512 + t;
    int r1 = r0 + 256;
    bool act0 = r0 < nneed, act1 = r1 < nneed;
    float4 p0q0, p0q1, p0q2, p0q3, p0q4;
    float4 p1q0, p1q1, p1q2, p1q3, p1q4;
    float M0 = 0.f, M1 = 0.f;
    float4 z4 = make_float4(0.f, 0.f, 0.f, 0.f);
    p0q0 = p0q1 = p0q2 = p0q3 = p0q4 = z4;
    p1q0 = p1q1 = p1q2 = p1q3 = p1q4 = z4;
    if (act0) {
        int n = g_need[r0];
        const float4* q = (const float4*)(g_xfq + (size_t)((b << 12) + n) * 20);
        p0q0 = q[0]; p0q1 = q[1]; p0q2 = q[2]; p0q3 = q[3]; p0q4 = q[4];
        M0 = g_M[(b << 12) + n];
    }
    if (act1) {
        int n = g_need[r1];
        const float4* q = (const float4*)(g_xfq + (size_t)((b << 12) + n) * 20);
        p1q0 = q[0]; p1q1 = q[1]; p1q2 = q[2]; p1q3 = q[3]; p1q4 = q[4];
        M1 = g_M[(b << 12) + n];
    }
    float l0 = 0.f, l1 = 0.f;
    float4 a0A = z4, a0B = z4; float a0C = 0.f;
    float4 a1A = z4, a1B = z4; float a1C = 0.f;
    for (int base = v0; base < v1; base += 256) {
        int cnt = min(256, v1 - base);
        if (t < cnt) {
            const float4* src = (const float4*)(g_wn + (size_t)((b << 12) + base + t) * 20);
            float4* dst = (float4*)(swn + t * 20);
            dst[0] = src[0]; dst[1] = src[1]; dst[2] = src[2]; dst[3] = src[3]; dst[4] = src[4];
            const float4* s2 = (const float4*)(g_xfe + (size_t)((b << 12) + base + t) * 12);
            float4* d2 = (float4*)(sxe + t * 12);
            d2[0] = s2[0]; d2[1] = s2[1]; d2[2] = s2[2];
        }
        __syncthreads();
        for (int j = 0; j < cnt; j++) {
            const float4* w = (const float4*)(swn + j * 20);
            float4 w0 = w[0], w1 = w[1], w2 = w[2], w3 = w[3];
            float2 w4 = *(const float2*)(swn + j * 20 + 16);
            const float4* xe = (const float4*)(sxe + j * 12);
            float4 x0 = xe[0], x1 = xe[1];
            float x2 = sxe[j * 12 + 8];
            // row 0 score (18 terms)
            float sa = p0q0.x * w0.x + p0q0.y * w0.y + p0q0.z * w0.z + p0q0.w * w0.w;
            float sb = p0q1.x * w1.x + p0q1.y * w1.y + p0q1.z * w1.z + p0q1.w * w1.w;
            float sc = p0q2.x * w2.x + p0q2.y * w2.y + p0q2.z * w2.z + p0q2.w * w2.w;
            float sd = p0q3.x * w3.x + p0q3.y * w3.y + p0q3.z * w3.z + p0q3.w * w3.w;
            float se = p0q4.x * w4.x + p0q4.y * w4.y;
            float sv0 = ((sa + sb) + (sc + sd)) + se;
            // row 1 score
            float ta = p1q0.x * w0.x + p1q0.y * w0.y + p1q0.z * w0.z + p1q0.w * w0.w;
            float tb = p1q1.x * w1.x + p1q1.y * w1.y + p1q1.z * w1.z + p1q1.w * w1.w;
            float tc = p1q2.x * w2.x + p1q2.y * w2.y + p1q2.z * w2.z + p1q2.w * w2.w;
            float td = p1q3.x * w3.x + p1q3.y * w3.y + p1q3.z * w3.z + p1q3.w * w3.w;
            float te = p1q4.x * w4.x + p1q4.y * w4.y;
            float sv1 = ((ta + tb) + (tc + td)) + te;
            float e0 = __expf(sv0 - M0);    // sv <= M always (||wn||<=1)
            float e1 = __expf(sv1 - M1);
            l0 += e0; l1 += e1;
            a0A.x = fmaf(e0, x0.x, a0A.x); a0A.y = fmaf(e0, x0.y, a0A.y);
            a0A.z = fmaf(e0, x0.z, a0A.z); a0A.w = fmaf(e0, x0.w, a0A.w);
            a0B.x = fmaf(e0, x1.x, a0B.x); a0B.y = fmaf(e0, x1.y, a0B.y);
            a0B.z = fmaf(e0, x1.z, a0B.z); a0B.w = fmaf(e0, x1.w, a0B.w);
            a0C   = fmaf(e0, x2,   a0C);
            a1A.x = fmaf(e1, x0.x, a1A.x); a1A.y = fmaf(e1, x0.y, a1A.y);
            a1A.z = fmaf(e1, x0.z, a1A.z); a1A.w = fmaf(e1, x0.w, a1A.w);
            a1B.x = fmaf(e1, x1.x, a1B.x); a1B.y = fmaf(e1, x1.y, a1B.y);
            a1B.z = fmaf(e1, x1.z, a1B.z); a1B.w = fmaf(e1, x1.w, a1B.w);
            a1C   = fmaf(e1, x2,   a1C);
        }
        __syncthreads();
    }
    if (act0) {
        int basei = ((b * SPLITS + s) << 12) + r0;
        g_pl[basei] = l0;
        float4* pa = (float4*)(g_pa + (size_t)basei * 12);
        pa[0] = a0A; pa[1] = a0B; pa[2] = make_float4(a0C, 0.f, 0.f, 0.f);
    }
    if (act1) {
        int basei = ((b * SPLITS + s) << 12) + r1;
        g_pl[basei] = l1;
        float4* pa = (float4*)(g_pa + (size_t)basei * 12);
        pa[0] = a1A; pa[1] = a1B; pa[2] = make_float4(a1C, 0.f, 0.f, 0.f);
    }
}

// ---------------- KE: deterministic split-K reduce + normalize ----------------
__global__ void kE_reduce() {
    int idx = blockIdx.x * blockDim.x + threadIdx.x;
    if (idx >= BB * PP) return;
    int b = idx >> 12, r = idx & 4095;
    if (r >= g_counts[1]) return;
    int n = g_need[r];
    int nvalid = g_counts[0];
    // masked keys each contribute exp(0 - M) to the softmax denominator
    float l = (float)(PP - nvalid) * __expf(-g_M[(b << 12) + n]);
    float acc[12];
    #pragma unroll
    for (int k = 0; k < 12; k++) acc[k] = 0.f;
    #pragma unroll
    for (int s = 0; s < SPLITS; s++) {
        int basei = ((b * SPLITS + s) << 12) + r;
        l += g_pl[basei];
        const float4* pa = (const float4*)(g_pa + (size_t)basei * 12);
        float4 q0 = pa[0], q1 = pa[1], q2 = pa[2];
        acc[0] += q0.x; acc[1] += q0.y; acc[2]  += q0.z; acc[3]  += q0.w;
        acc[4] += q1.x; acc[5] += q1.y; acc[6]  += q1.z; acc[7]  += q1.w;
        acc[8] += q2.x;
    }
    float rl = 1.f / l;
    float* dst = g_tmp9 + (size_t)((b << 12) + n) * 9;
    #pragma unroll
    for (int k = 0; k < 9; k++) dst[k] = acc[k] * rl;
}

// ---------------- KF: fused gate conv + transpose-conv gather + final elementwise ----------------
// One warp per pixel: lanes split the 49 gate taps and 9 y0 taps, butterfly
// reduce, then each lane writes one float4 of the 128 channels.
__global__ void kF_final(const float* __restrict__ inp, const float* __restrict__ mask,
                         const float* __restrict__ bias, const float* __restrict__ convw,
                         float* __restrict__ out) {
    int gw = blockIdx.x * 8 + (threadIdx.x >> 5);   // pixel index b*4096+p
    int lane = threadIdx.x & 31;
    int b = gw >> 12, p = gw & 4095, y = p >> 6, x = p & 63;
    float mv = mask[p];
    float gsum = 0.f, ysum = 0.f;
    #pragma unroll
    for (int tt = 0; tt < 2; tt++) {
        int tp = lane + tt * 32;
        if (tp < 49) {
            int u = tp / 7, v = tp % 7;
            int yy = y + u - 3, xx = x + v - 3;
            if (yy >= 0 && yy < HH && xx >= 0 && xx < WW) {
                int q = (b << 12) + (yy << 6) + xx;
                gsum += g_x[q * 2 + 0] * __ldg(convw + tp * 2 + 0)
                      + g_x[q * 2 + 1] * __ldg(convw + tp * 2 + 1);
            }
        }
    }
    if (mv < 0.5f && lane < 9) {
        int kh = lane / 3, kw = lane % 3;
        int ny = y - (kh - 1), nx = x - (kw - 1);
        if (ny >= 0 && ny < HH && nx >= 0 && nx < WW)
            ysum = g_tmp9[(size_t)((b << 12) + (ny << 6) + nx) * 9 + lane];
    }
    #pragma unroll
    for (int o = 16; o; o >>= 1) {
        gsum += __shfl_xor_sync(0xffffffffu, gsum, o);
        ysum += __shfl_xor_sync(0xffffffffu, ysum, o);
    }
    float sg = 1.f / (1.f + __expf(-gsum));
    float yb = ysum * 0.25f;
    float w = 1.0f - mv;
    int i4 = (gw << 5) + lane;
    float4 iv = ((const float4*)inp)[i4];
    float4 bv = ((const float4*)bias)[(p << 5) + lane];
    float4 o4;
    o4.x = sg * (iv.x + (yb + bv.x) * w);
    o4.y = sg * (iv.y + (yb + bv.y) * w);
    o4.z = sg * (iv.z + (yb + bv.z) * w);
    o4.w = sg * (iv.w + (yb + bv.w) * w);
    ((float4*)out)[i4] = o4;
}

// ---------------- launch ----------------
extern "C" void kernel_launch(void* const* d_in, const int* in_sizes, int n_in,
                              void* d_out, int out_size) {
    const float* inp   = (const float*)d_in[0];
    const float* mask  = (const float*)d_in[1];
    const float* bias  = (const float*)d_in[2];
    const float* convw = (const float*)d_in[3];
    float* out = (float*)d_out;

    kA<<<2049, 256>>>(inp, mask);
    kB_patches<<<(BB * PP) / 256, 256>>>();
    kC_keys<<<(BB * PP * 8) / 256, 256>>>();
    dim3 gD((PP + 511) / 512, BB, SPLITS);
    kD_attn<<<gD, 256>>>();
    kE_reduce<<<(BB * PP) / 256, 256>>>();
    kF_final<<<(BB * PP) / 8, 256>>>(inp, mask, bias, convw, out);
}

// round 5
// speedup vs baseline: 1.4414x; 1.0583x over previous
#include <cuda_runtime.h>
#include <math.h>

#define BB 4
#define HH 64
#define WW 64
#define CC 128
#define PP 4096
#define SPLITS 16
#define LOG2E 1.44269504088896340736f

typedef unsigned long long ull;

// ---------------- static scratch ----------------
__device__ float g_x[BB * PP * 2];          // per-pixel (mean, max)
__device__ float g_xfq[BB * PP * 20];       // padded 18-dim patch vectors (queries)
__device__ float g_M[BB * PP];              // L2 norm of each patch
__device__ float g_wn[BB * PP * 20];        // compacted normalized keys, 18 + 2 pad
__device__ float g_xfd[BB * PP * 20];       // compacted DUPLICATED value taps: (xf0,xf0,xf2,xf2,...), 18+2 pad
__device__ int   g_valid[PP];
__device__ int   g_need[PP];
__device__ int   g_counts[2];
__device__ float g_pl[BB * SPLITS * PP];
__device__ float g_pa[(size_t)BB * SPLITS * PP * 12];
__device__ float g_tmp9[BB * PP * 9];

// ---- packed f32x2 helpers ----
__device__ __forceinline__ ull pk2(float lo, float hi) {
    ull r; asm("mov.b64 %0, {%1, %2};" : "=l"(r) : "f"(lo), "f"(hi)); return r;
}
__device__ __forceinline__ void upk(ull v, float& lo, float& hi) {
    asm("mov.b64 {%0, %1}, %2;" : "=f"(lo), "=f"(hi) : "l"(v));
}
__device__ __forceinline__ ull f2fma(ull a, ull b, ull c) {
    ull d; asm("fma.rn.f32x2 %0, %1, %2, %3;" : "=l"(d) : "l"(a), "l"(b), "l"(c)); return d;
}
__device__ __forceinline__ ull f2mul(ull a, ull b) {
    ull d; asm("mul.rn.f32x2 %0, %1, %2;" : "=l"(d) : "l"(a), "l"(b)); return d;
}
__device__ __forceinline__ ull f2add(ull a, ull b) {
    ull d; asm("add.rn.f32x2 %0, %1, %2;" : "=l"(d) : "l"(a), "l"(b)); return d;
}
__device__ __forceinline__ float ex2f(float x) {
    float r; asm("ex2.approx.f32 %0, %1;" : "=f"(r) : "f"(x)); return r;
}

// ---------------- KA: mean/max (blocks 0..2047) + compaction (block 2048) ----------------
__global__ void kA(const float* __restrict__ inp, const float* __restrict__ mask) {
    __shared__ int wv[8], wn_[8];
    if (blockIdx.x == 2048) {
        int t = threadIdx.x;
        int lane = t & 31, wid = t >> 5;
        unsigned fv = 0, fn = 0;
        int cv = 0, cn = 0;
        int base_p = t * 16;
        for (int i = 0; i < 16; i++) {
            int p = base_p + i, y = p >> 6, x = p & 63;
            int allone = 1, anyz = 0;
            #pragma unroll
            for (int dy = -1; dy <= 1; dy++)
                #pragma unroll
                for (int dx = -1; dx <= 1; dx++) {
                    int yy = y + dy, xx = x + dx;
                    if (yy < 0 || yy >= HH || xx < 0 || xx >= WW) {
                        allone = 0;
                    } else {
                        float mv = mask[(yy << 6) + xx];
                        if (mv < 0.5f) { allone = 0; anyz = 1; }
                    }
                }
            if (allone) { fv |= (1u << i); cv++; }
            if (anyz)   { fn |= (1u << i); cn++; }
        }
        int iv = cv, inn = cn;
        #pragma unroll
        for (int o = 1; o < 32; o <<= 1) {
            int a = __shfl_up_sync(0xffffffffu, iv, o);
            int b = __shfl_up_sync(0xffffffffu, inn, o);
            if (lane >= o) { iv += a; inn += b; }
        }
        if (lane == 31) { wv[wid] = iv; wn_[wid] = inn; }
        __syncthreads();
        int bv = 0, bn = 0;
        for (int i = 0; i < wid; i++) { bv += wv[i]; bn += wn_[i]; }
        int offv = bv + iv - cv;
        int offn = bn + inn - cn;
        for (int i = 0; i < 16; i++) {
            if (fv & (1u << i)) g_valid[offv++] = base_p + i;
            if (fn & (1u << i)) g_need[offn++]  = base_p + i;
        }
        if (t == 255) { g_counts[0] = bv + iv; g_counts[1] = bn + inn; }
        return;
    }
    int warp = blockIdx.x * 8 + (threadIdx.x >> 5);
    int lane = threadIdx.x & 31;
    const float4* base = (const float4*)(inp + (size_t)warp * CC);
    float4 v = base[lane];
    float s = (v.x + v.y) + (v.z + v.w);
    float m = fmaxf(fmaxf(v.x, v.y), fmaxf(v.z, v.w));
    #pragma unroll
    for (int o = 16; o; o >>= 1) {
        s += __shfl_xor_sync(0xffffffffu, s, o);
        m = fmaxf(m, __shfl_xor_sync(0xffffffffu, m, o));
    }
    if (lane == 0) {
        g_x[warp * 2 + 0] = s * (1.0f / 128.0f);
        g_x[warp * 2 + 1] = m;
    }
}

// ---------------- KB: patch vectors + norms ----------------
__global__ void kB_patches() {
    int idx = blockIdx.x * blockDim.x + threadIdx.x;
    if (idx >= BB * PP) return;
    int p = idx & 4095, y = p >> 6, x = p & 63;
    int b = idx >> 12;
    float v[18];
    float ss = 0.f;
    int j = 0;
    #pragma unroll
    for (int kh = 0; kh < 3; kh++)
        #pragma unroll
        for (int kw = 0; kw < 3; kw++) {
            int yy = y + kh - 1, xx = x + kw - 1;
            float a = 0.f, c1 = 0.f;
            if (yy >= 0 && yy < HH && xx >= 0 && xx < WW) {
                int q = (b << 12) + (yy << 6) + xx;
                a  = g_x[q * 2 + 0];
                c1 = g_x[q * 2 + 1];
            }
            v[j] = a; v[j + 1] = c1;
            ss += a * a + c1 * c1;
            j += 2;
        }
    float* dst = g_xfq + (size_t)idx * 20;
    #pragma unroll
    for (int i = 0; i < 18; i++) dst[i] = v[i];
    dst[18] = 0.f; dst[19] = 0.f;
    g_M[idx] = sqrtf(ss);
}

// ---------------- KC: compact normalized keys + duplicated value taps, 8 threads/key ----------------
__global__ void kC_keys() {
    int tid = blockIdx.x * blockDim.x + threadIdx.x;   // BB*PP*8
    int key = tid >> 3, w = tid & 7;
    int b = key >> 12, v = key & 4095;
    if (v >= g_counts[0]) return;
    int p = g_valid[v];
    int srcI = (b << 12) + p;
    const float4* src = (const float4*)(g_xfq + (size_t)srcI * 20);
    int dstI = (b << 12) + v;
    if (w < 5) {
        float rn = 1.f / fmaxf(g_M[srcI], 1e-4f);
        float4 sv = src[w];                 // pad words stay 0
        ((float4*)(g_wn + (size_t)dstI * 20))[w] =
            make_float4(sv.x * rn, sv.y * rn, sv.z * rn, sv.w * rn);
    } else if (w == 5) {
        float4 s0 = src[0], s1 = src[1];
        float4* d = (float4*)(g_xfd + (size_t)dstI * 20);
        d[0] = make_float4(s0.x, s0.x, s0.z, s0.z);
        d[1] = make_float4(s1.x, s1.x, s1.z, s1.z);
    } else if (w == 6) {
        float4 s2 = src[2], s3 = src[3];
        float4* d = (float4*)(g_xfd + (size_t)dstI * 20);
        d[2] = make_float4(s2.x, s2.x, s2.z, s2.z);
        d[3] = make_float4(s3.x, s3.x, s3.z, s3.z);
    } else {
        float4 s4 = src[4];
        float4* d = (float4*)(g_xfd + (size_t)dstI * 20);
        d[4] = make_float4(s4.x, s4.x, 0.f, 0.f);
    }
}

// ---------------- KD: fused attention, packed f32x2, 4 rows/thread ----------------
__global__ void __launch_bounds__(128, 3) kD_attn() {
    __shared__ ulonglong2 swn[256 * 5];   // 9 packed dim-pairs + pad per key
    __shared__ ulonglong2 sxd[256 * 5];   // 9 duplicated taps + pad per key
    int nneed = g_counts[1];
    if ((int)(blockIdx.x * 512) >= nneed) return;
    int nvalid = g_counts[0];
    int b = blockIdx.y, s = blockIdx.z;
    int chunk = (nvalid + SPLITS - 1) / SPLITS;
    int v0 = s * chunk;
    int v1 = min(v0 + chunk, nvalid);
    int t = threadIdx.x;

    int r[4]; bool act[4];
    ull q[4][9];
    float M2[4];
    ull zero = pk2(0.f, 0.f);
    #pragma unroll
    for (int i = 0; i < 4; i++) {
        r[i] = blockIdx.x * 512 + i * 128 + t;
        act[i] = r[i] < nneed;
        if (act[i]) {
            int n = g_need[r[i]];
            const float4* qp = (const float4*)(g_xfq + (size_t)((b << 12) + n) * 20);
            float4 f0 = qp[0], f1 = qp[1], f2 = qp[2], f3 = qp[3], f4 = qp[4];
            q[i][0] = pk2(f0.x * LOG2E, f0.y * LOG2E);
            q[i][1] = pk2(f0.z * LOG2E, f0.w * LOG2E);
            q[i][2] = pk2(f1.x * LOG2E, f1.y * LOG2E);
            q[i][3] = pk2(f1.z * LOG2E, f1.w * LOG2E);
            q[i][4] = pk2(f2.x * LOG2E, f2.y * LOG2E);
            q[i][5] = pk2(f2.z * LOG2E, f2.w * LOG2E);
            q[i][6] = pk2(f3.x * LOG2E, f3.y * LOG2E);
            q[i][7] = pk2(f3.z * LOG2E, f3.w * LOG2E);
            q[i][8] = pk2(f4.x * LOG2E, f4.y * LOG2E);
            M2[i] = g_M[(b << 12) + n] * LOG2E;
        } else {
            #pragma unroll
            for (int k = 0; k < 9; k++) q[i][k] = zero;
            M2[i] = 0.f;
        }
    }
    ull l01 = zero, l23 = zero;
    ull a01[9], a23[9];
    #pragma unroll
    for (int k = 0; k < 9; k++) { a01[k] = zero; a23[k] = zero; }

    for (int base = v0; base < v1; base += 256) {
        int cnt = min(256, v1 - base);
        for (int kk = t; kk < cnt; kk += 128) {
            const ulonglong2* srcw = (const ulonglong2*)(g_wn  + (size_t)((b << 12) + base + kk) * 20);
            const ulonglong2* srcx = (const ulonglong2*)(g_xfd + (size_t)((b << 12) + base + kk) * 20);
            #pragma unroll
            for (int w = 0; w < 5; w++) {
                swn[kk * 5 + w] = srcw[w];
                sxd[kk * 5 + w] = srcx[w];
            }
        }
        __syncthreads();
        for (int j = 0; j < cnt; j++) {
            const ulonglong2* wp = &swn[j * 5];
            ulonglong2 wa = wp[0], wb = wp[1], wc = wp[2], wd = wp[3];
            ull w8 = wp[4].x;
            ull sv[4];
            #pragma unroll
            for (int i = 0; i < 4; i++) {
                ull acc = f2mul(q[i][0], wa.x);
                acc = f2fma(q[i][1], wa.y, acc);
                acc = f2fma(q[i][2], wb.x, acc);
                acc = f2fma(q[i][3], wb.y, acc);
                acc = f2fma(q[i][4], wc.x, acc);
                acc = f2fma(q[i][5], wc.y, acc);
                acc = f2fma(q[i][6], wd.x, acc);
                acc = f2fma(q[i][7], wd.y, acc);
                sv[i] = f2fma(q[i][8], w8, acc);
            }
            float e[4];
            #pragma unroll
            for (int i = 0; i < 4; i++) {
                float lo, hi;
                upk(sv[i], lo, hi);
                e[i] = ex2f((lo + hi) - M2[i]);     // score <= M always
            }
            ull e01 = pk2(e[0], e[1]);
            ull e23 = pk2(e[2], e[3]);
            l01 = f2add(l01, e01);
            l23 = f2add(l23, e23);
            const ulonglong2* xp = &sxd[j * 5];
            ulonglong2 xa = xp[0], xb = xp[1], xc = xp[2], xd = xp[3];
            ull x8 = xp[4].x;
            a01[0] = f2fma(e01, xa.x, a01[0]); a23[0] = f2fma(e23, xa.x, a23[0]);
            a01[1] = f2fma(e01, xa.y, a01[1]); a23[1] = f2fma(e23, xa.y, a23[1]);
            a01[2] = f2fma(e01, xb.x, a01[2]); a23[2] = f2fma(e23, xb.x, a23[2]);
            a01[3] = f2fma(e01, xb.y, a01[3]); a23[3] = f2fma(e23, xb.y, a23[3]);
            a01[4] = f2fma(e01, xc.x, a01[4]); a23[4] = f2fma(e23, xc.x, a23[4]);
            a01[5] = f2fma(e01, xc.y, a01[5]); a23[5] = f2fma(e23, xc.y, a23[5]);
            a01[6] = f2fma(e01, xd.x, a01[6]); a23[6] = f2fma(e23, xd.x, a23[6]);
            a01[7] = f2fma(e01, xd.y, a01[7]); a23[7] = f2fma(e23, xd.y, a23[7]);
            a01[8] = f2fma(e01, x8,   a01[8]); a23[8] = f2fma(e23, x8,   a23[8]);
        }
        __syncthreads();
    }

    float lv[4];
    upk(l01, lv[0], lv[1]);
    upk(l23, lv[2], lv[3]);
    float av[4][9];
    #pragma unroll
    for (int k = 0; k < 9; k++) {
        upk(a01[k], av[0][k], av[1][k]);
        upk(a23[k], av[2][k], av[3][k]);
    }
    #pragma unroll
    for (int i = 0; i < 4; i++) {
        if (!act[i]) continue;
        int basei = ((b * SPLITS + s) << 12) + r[i];
        g_pl[basei] = lv[i];
        float4* pa = (float4*)(g_pa + (size_t)basei * 12);
        pa[0] = make_float4(av[i][0], av[i][1], av[i][2], av[i][3]);
        pa[1] = make_float4(av[i][4], av[i][5], av[i][6], av[i][7]);
        pa[2] = make_float4(av[i][8], 0.f, 0.f, 0.f);
    }
}

// ---------------- KE: deterministic split-K reduce + normalize ----------------
__global__ void kE_reduce() {
    int idx = blockIdx.x * blockDim.x + threadIdx.x;
    if (idx >= BB * PP) return;
    int b = idx >> 12, r = idx & 4095;
    if (r >= g_counts[1]) return;
    int n = g_need[r];
    int nvalid = g_counts[0];
    float l = (float)(PP - nvalid) * __expf(-g_M[(b << 12) + n]);
    float acc[9];
    #pragma unroll
    for (int k = 0; k < 9; k++) acc[k] = 0.f;
    #pragma unroll
    for (int s = 0; s < SPLITS; s++) {
        int basei = ((b * SPLITS + s) << 12) + r;
        l += g_pl[basei];
        const float4* pa = (const float4*)(g_pa + (size_t)basei * 12);
        float4 q0 = pa[0], q1 = pa[1], q2 = pa[2];
        acc[0] += q0.x; acc[1] += q0.y; acc[2] += q0.z; acc[3] += q0.w;
        acc[4] += q1.x; acc[5] += q1.y; acc[6] += q1.z; acc[7] += q1.w;
        acc[8] += q2.x;
    }
    float rl = 1.f / l;
    float* dst = g_tmp9 + (size_t)((b << 12) + n) * 9;
    #pragma unroll
    for (int k = 0; k < 9; k++) dst[k] = acc[k] * rl;
}

// ---------------- KF: fused gate conv + transpose-conv + final elementwise ----------------
__global__ void kF_final(const float* __restrict__ inp, const float* __restrict__ mask,
                         const float* __restrict__ bias, const float* __restrict__ convw,
                         float* __restrict__ out) {
    int gw = blockIdx.x * 8 + (threadIdx.x >> 5);
    int lane = threadIdx.x & 31;
    int b = gw >> 12, p = gw & 4095, y = p >> 6, x = p & 63;
    float mv = mask[p];
    float gsum = 0.f, ysum = 0.f;
    #pragma unroll
    for (int tt = 0; tt < 2; tt++) {
        int tp = lane + tt * 32;
        if (tp < 49) {
            int u = tp / 7, v = tp % 7;
            int yy = y + u - 3, xx = x + v - 3;
            if (yy >= 0 && yy < HH && xx >= 0 && xx < WW) {
                int q = (b << 12) + (yy << 6) + xx;
                gsum += g_x[q * 2 + 0] * __ldg(convw + tp * 2 + 0)
                      + g_x[q * 2 + 1] * __ldg(convw + tp * 2 + 1);
            }
        }
    }
    if (mv < 0.5f && lane < 9) {
        int kh = lane / 3, kw = lane % 3;
        int ny = y - (kh - 1), nx = x - (kw - 1);
        if (ny >= 0 && ny < HH && nx >= 0 && nx < WW)
            ysum = g_tmp9[(size_t)((b << 12) + (ny << 6) + nx) * 9 + lane];
    }
    #pragma unroll
    for (int o = 16; o; o >>= 1) {
        gsum += __shfl_xor_sync(0xffffffffu, gsum, o);
        ysum += __shfl_xor_sync(0xffffffffu, ysum, o);
    }
    float sg = 1.f / (1.f + __expf(-gsum));
    float yb = ysum * 0.25f;
    float w = 1.0f - mv;
    int i4 = (gw << 5) + lane;
    float4 iv = ((const float4*)inp)[i4];
    float4 bv = ((const float4*)bias)[(p << 5) + lane];
    float4 o4;
    o4.x = sg * (iv.x + (yb + bv.x) * w);
    o4.y = sg * (iv.y + (yb + bv.y) * w);
    o4.z = sg * (iv.z + (yb + bv.z) * w);
    o4.w = sg * (iv.w + (yb + bv.w) * w);
    ((float4*)out)[i4] = o4;
}

// ---------------- launch ----------------
extern "C" void kernel_launch(void* const* d_in, const int* in_sizes, int n_in,
                              void* d_out, int out_size) {
    const float* inp   = (const float*)d_in[0];
    const float* mask  = (const float*)d_in[1];
    const float* bias  = (const float*)d_in[2];
    const float* convw = (const float*)d_in[3];
    float* out = (float*)d_out;

    kA<<<2049, 256>>>(inp, mask);
    kB_patches<<<(BB * PP) / 256, 256>>>();
    kC_keys<<<(BB * PP * 8) / 256, 256>>>();
    dim3 gD(8, BB, SPLITS);
    kD_attn<<<gD, 128>>>();
    kE_reduce<<<(BB * PP) / 256, 256>>>();
    kF_final<<<(BB * PP) / 8, 256>>>(inp, mask, bias, convw, out);
}

// round 7
// speedup vs baseline: 1.5315x; 1.0625x over previous
#include <cuda_runtime.h>
#include <math.h>

#define BB 4
#define HH 64
#define WW 64
#define CC 128
#define PP 4096
#define SPLITS 12
#define GX 32
#define ROWS_PB 128
#define LOG2E 1.44269504088896340736f

typedef unsigned long long ull;

// ---------------- static scratch ----------------
__device__ float g_x[BB * PP * 2];          // per-pixel (mean, max)
__device__ float g_xfq[BB * PP * 20];       // queries pre-scaled by LOG2E, dim-pairs, 18+2 pad
__device__ float g_M[BB * PP];              // M2 = patch L2 norm * LOG2E
__device__ float g_wn[BB * PP * 20];        // compacted normalized keys, 18+2 pad
__device__ float g_xfe[BB * PP * 12];       // compacted taps [t0..t8, 1.0, 0, 0]
__device__ int   g_vrank[PP];               // pixel -> compacted key index (or -1)
__device__ int   g_need[PP];
__device__ int   g_counts[2];               // [0]=n_valid, [1]=n_need
__device__ ull   g_pa[(size_t)BB * SPLITS * PP * 5];  // packed split partials (9 taps + l)
__device__ float g_tmp9[BB * PP * 9];
__device__ int   g_cnt[BB * GX];            // split arrival counters (self-resetting)

// ---- packed f32x2 helpers ----
__device__ __forceinline__ ull pk2(float lo, float hi) {
    ull r; asm("mov.b64 %0, {%1, %2};" : "=l"(r) : "f"(lo), "f"(hi)); return r;
}
__device__ __forceinline__ void upk(ull v, float& lo, float& hi) {
    asm("mov.b64 {%0, %1}, %2;" : "=f"(lo), "=f"(hi) : "l"(v));
}
__device__ __forceinline__ ull f2fma(ull a, ull b, ull c) {
    ull d; asm("fma.rn.f32x2 %0, %1, %2, %3;" : "=l"(d) : "l"(a), "l"(b), "l"(c)); return d;
}
__device__ __forceinline__ ull f2mul(ull a, ull b) {
    ull d; asm("mul.rn.f32x2 %0, %1, %2;" : "=l"(d) : "l"(a), "l"(b)); return d;
}
__device__ __forceinline__ ull f2add(ull a, ull b) {
    ull d; asm("add.rn.f32x2 %0, %1, %2;" : "=l"(d) : "l"(a), "l"(b)); return d;
}
__device__ __forceinline__ float ex2f(float x) {
    float r; asm("ex2.approx.f32 %0, %1;" : "=f"(r) : "f"(x)); return r;
}

// ---------------- KA: mean/max (blocks 0..2047) + compaction+vrank (block 2048) ----------------
__global__ void kA(const float* __restrict__ inp, const float* __restrict__ mask) {
    __shared__ int wv[8], wn_[8];
    if (blockIdx.x == 2048) {
        int t = threadIdx.x;
        int lane = t & 31, wid = t >> 5;
        unsigned fv = 0, fn = 0;
        int cv = 0, cn = 0;
        int base_p = t * 16;
        for (int i = 0; i < 16; i++) {
            int p = base_p + i, y = p >> 6, x = p & 63;
            int allone = 1, anyz = 0;
            #pragma unroll
            for (int dy = -1; dy <= 1; dy++)
                #pragma unroll
                for (int dx = -1; dx <= 1; dx++) {
                    int yy = y + dy, xx = x + dx;
                    if (yy < 0 || yy >= HH || xx < 0 || xx >= WW) {
                        allone = 0;
                    } else {
                        float mv = mask[(yy << 6) + xx];
                        if (mv < 0.5f) { allone = 0; anyz = 1; }
                    }
                }
            if (allone) { fv |= (1u << i); cv++; }
            if (anyz)   { fn |= (1u << i); cn++; }
        }
        int iv = cv, inn = cn;
        #pragma unroll
        for (int o = 1; o < 32; o <<= 1) {
            int a = __shfl_up_sync(0xffffffffu, iv, o);
            int b = __shfl_up_sync(0xffffffffu, inn, o);
            if (lane >= o) { iv += a; inn += b; }
        }
        if (lane == 31) { wv[wid] = iv; wn_[wid] = inn; }
        __syncthreads();
        int bv = 0, bn = 0;
        for (int i = 0; i < wid; i++) { bv += wv[i]; bn += wn_[i]; }
        int offv = bv + iv - cv;
        int offn = bn + inn - cn;
        for (int i = 0; i < 16; i++) {
            int p = base_p + i;
            if (fv & (1u << i)) g_vrank[p] = offv++;
            else                g_vrank[p] = -1;
            if (fn & (1u << i)) g_need[offn++] = p;
        }
        if (t == 255) { g_counts[0] = bv + iv; g_counts[1] = bn + inn; }
        return;
    }
    int warp = blockIdx.x * 8 + (threadIdx.x >> 5);
    int lane = threadIdx.x & 31;
    const float4* base = (const float4*)(inp + (size_t)warp * CC);
    float4 v = base[lane];
    float s = (v.x + v.y) + (v.z + v.w);
    float m = fmaxf(fmaxf(v.x, v.y), fmaxf(v.z, v.w));
    #pragma unroll
    for (int o = 16; o; o >>= 1) {
        s += __shfl_xor_sync(0xffffffffu, s, o);
        m = fmaxf(m, __shfl_xor_sync(0xffffffffu, m, o));
    }
    if (lane == 0) {
        g_x[warp * 2 + 0] = s * (1.0f / 128.0f);
        g_x[warp * 2 + 1] = m;
    }
}

// ---------------- KB: patch vectors + norms + (fused) compacted keys/values ----------------
__global__ void kB_patches() {
    int idx = blockIdx.x * blockDim.x + threadIdx.x;   // BB*PP
    if (idx >= BB * PP) return;
    int p = idx & 4095, y = p >> 6, x = p & 63;
    int b = idx >> 12;
    float v[18];
    float ss = 0.f;
    int j = 0;
    #pragma unroll
    for (int kh = 0; kh < 3; kh++)
        #pragma unroll
        for (int kw = 0; kw < 3; kw++) {
            int yy = y + kh - 1, xx = x + kw - 1;
            float a = 0.f, c1 = 0.f;
            if (yy >= 0 && yy < HH && xx >= 0 && xx < WW) {
                int q = (b << 12) + (yy << 6) + xx;
                a  = g_x[q * 2 + 0];
                c1 = g_x[q * 2 + 1];
            }
            v[j] = a; v[j + 1] = c1;
            ss += a * a + c1 * c1;
            j += 2;
        }
    float Mn = sqrtf(ss);
    // query: pre-scaled by LOG2E
    float* dst = g_xfq + (size_t)idx * 20;
    #pragma unroll
    for (int i = 0; i < 18; i++) dst[i] = v[i] * LOG2E;
    dst[18] = 0.f; dst[19] = 0.f;
    g_M[idx] = Mn * LOG2E;
    // key/value if this pixel is a fully-valid patch
    int vr = g_vrank[p];
    if (vr >= 0) {
        float rn = 1.f / fmaxf(Mn, 1e-4f);
        float* dw = g_wn + (size_t)((b << 12) + vr) * 20;
        #pragma unroll
        for (int i = 0; i < 18; i++) dw[i] = v[i] * rn;
        dw[18] = 0.f; dw[19] = 0.f;
        float* de = g_xfe + (size_t)((b << 12) + vr) * 12;
        #pragma unroll
        for (int k = 0; k < 9; k++) de[k] = v[2 * k];
        de[9] = 1.0f;          // synthetic tap: accumulates the softmax denominator
        de[10] = 0.f; de[11] = 0.f;
    }
}

// ---------------- KD: fused attention (f32x2, 1 row/thread) + last-block split reduce ----------------
__global__ void __launch_bounds__(128, 6) kD_attn() {
    __shared__ ulonglong2 swn[128 * 5];  // key dim-pairs (w0,w1)(w2,w3)(w4,w5)(w6,w7)(w8,pad)
    __shared__ ulonglong2 sxe[128 * 3];  // tap pairs (t0,t1)(t2,t3)(t4,t5)(t6,t7)(t8,1.0)(pad)
    __shared__ int s_win;
    int nneed = g_counts[1];
    int x = blockIdx.x, b = blockIdx.y, s = blockIdx.z;
    if (x * ROWS_PB >= nneed) return;
    int nvalid = g_counts[0];
    int chunk = (nvalid + SPLITS - 1) / SPLITS;
    int v0 = s * chunk;
    int v1 = min(v0 + chunk, nvalid);
    int t = threadIdx.x;
    int r = x * ROWS_PB + t;
    bool act = r < nneed;

    // load query (g_need entries are always in [0,4095]; inactive results discarded)
    ull q0, q1, q2, q3, q4, q5, q6, q7, q8;
    float M2;
    {
        int n = g_need[r];
        const ulonglong2* qp = (const ulonglong2*)(g_xfq + (size_t)((b << 12) + n) * 20);
        ulonglong2 a_ = qp[0], b_ = qp[1], c_ = qp[2], d_ = qp[3], e_ = qp[4];
        q0 = a_.x; q1 = a_.y; q2 = b_.x; q3 = b_.y; q4 = c_.x;
        q5 = c_.y; q6 = d_.x; q7 = d_.y; q8 = e_.x;
        M2 = g_M[(b << 12) + n];
    }
    ull a0 = pk2(0.f, 0.f), a1 = a0, a2 = a0, a3 = a0, a4 = a0;

    for (int base = v0; base < v1; base += 128) {
        int cnt = min(128, v1 - base);
        __syncthreads();
        if (t < cnt) {
            const ulonglong2* srcw = (const ulonglong2*)(g_wn + (size_t)((b << 12) + base + t) * 20);
            #pragma unroll
            for (int w = 0; w < 5; w++) swn[t * 5 + w] = srcw[w];
            const ulonglong2* srcx = (const ulonglong2*)(g_xfe + (size_t)((b << 12) + base + t) * 12);
            #pragma unroll
            for (int w = 0; w < 3; w++) sxe[t * 3 + w] = srcx[w];
        }
        __syncthreads();
        for (int j = 0; j < cnt; j++) {
            ulonglong2 wa = swn[j * 5], wb = swn[j * 5 + 1], wc = swn[j * 5 + 2], wd = swn[j * 5 + 3];
            ull w8 = swn[j * 5 + 4].x;
            ull acc = f2mul(q0, wa.x);
            acc = f2fma(q1, wa.y, acc);
            acc = f2fma(q2, wb.x, acc);
            acc = f2fma(q3, wb.y, acc);
            acc = f2fma(q4, wc.x, acc);
            acc = f2fma(q5, wc.y, acc);
            acc = f2fma(q6, wd.x, acc);
            acc = f2fma(q7, wd.y, acc);
            acc = f2fma(q8, w8, acc);
            float lo, hi;
            upk(acc, lo, hi);
            float e = ex2f((lo + hi) - M2);      // score <= M always (||wn||<=1)
            ull ee = pk2(e, e);
            ulonglong2 xa = sxe[j * 3], xb = sxe[j * 3 + 1], xc = sxe[j * 3 + 2];
            a0 = f2fma(ee, xa.x, a0);
            a1 = f2fma(ee, xa.y, a1);
            a2 = f2fma(ee, xb.x, a2);
            a3 = f2fma(ee, xb.y, a3);
            a4 = f2fma(ee, xc.x, a4);            // (t8, 1.0) -> (acc8, l)
        }
    }
    if (act) {
        ull* pa = g_pa + ((size_t)((b * SPLITS + s) << 12) + r) * 5;
        pa[0] = a0; pa[1] = a1; pa[2] = a2; pa[3] = a3; pa[4] = a4;
    }
    // split-arrival; last block of this (b,x) group reduces (fixed s order => deterministic)
    __syncthreads();
    if (t == 0) {
        __threadfence();
        int old = atomicAdd(&g_cnt[b * GX + x], 1);
        s_win = (old == SPLITS - 1) ? 1 : 0;
        if (s_win) g_cnt[b * GX + x] = 0;        // reset for next graph replay
    }
    __syncthreads();
    if (s_win && act) {
        int n = g_need[r];
        float M2v = g_M[(b << 12) + n];
        ull c0 = pk2(0.f, 0.f), c1 = c0, c2 = c0, c3 = c0;
        ull c4 = pk2(0.f, (float)(PP - nvalid) * ex2f(-M2v));  // masked keys' denominator
        #pragma unroll
        for (int ss2 = 0; ss2 < SPLITS; ss2++) {
            const ull* pa = g_pa + ((size_t)((b * SPLITS + ss2) << 12) + r) * 5;
            c0 = f2add(c0, pa[0]);
            c1 = f2add(c1, pa[1]);
            c2 = f2add(c2, pa[2]);
            c3 = f2add(c3, pa[3]);
            c4 = f2add(c4, pa[4]);
        }
        float f[10];
        upk(c0, f[0], f[1]);
        upk(c1, f[2], f[3]);
        upk(c2, f[4], f[5]);
        upk(c3, f[6], f[7]);
        upk(c4, f[8], f[9]);
        float rl = 1.f / f[9];
        float* dst = g_tmp9 + (size_t)((b << 12) + n) * 9;
        #pragma unroll
        for (int k = 0; k < 9; k++) dst[k] = f[k] * rl;
    }
}

// ---------------- KF: fused gate conv + transpose-conv + final elementwise ----------------
__global__ void kF_final(const float* __restrict__ inp, const float* __restrict__ mask,
                         const float* __restrict__ bias, const float* __restrict__ convw,
                         float* __restrict__ out) {
    int gw = blockIdx.x * 8 + (threadIdx.x >> 5);
    int lane = threadIdx.x & 31;
    int b = gw >> 12, p = gw & 4095, y = p >> 6, x = p & 63;
    float mv = mask[p];
    float gsum = 0.f, ysum = 0.f;
    #pragma unroll
    for (int tt = 0; tt < 2; tt++) {
        int tp = lane + tt * 32;
        if (tp < 49) {
            int u = tp / 7, v = tp % 7;
            int yy = y + u - 3, xx = x + v - 3;
            if (yy >= 0 && yy < HH && xx >= 0 && xx < WW) {
                int q = (b << 12) + (yy << 6) + xx;
                gsum += g_x[q * 2 + 0] * __ldg(convw + tp * 2 + 0)
                      + g_x[q * 2 + 1] * __ldg(convw + tp * 2 + 1);
            }
        }
    }
    if (mv < 0.5f && lane < 9) {
        int kh = lane / 3, kw = lane % 3;
        int ny = y - (kh - 1), nx = x - (kw - 1);
        if (ny >= 0 && ny < HH && nx >= 0 && nx < WW)
            ysum = g_tmp9[(size_t)((b << 12) + (ny << 6) + nx) * 9 + lane];
    }
    #pragma unroll
    for (int o = 16; o; o >>= 1) {
        gsum += __shfl_xor_sync(0xffffffffu, gsum, o);
        ysum += __shfl_xor_sync(0xffffffffu, ysum, o);
    }
    float sg = 1.f / (1.f + __expf(-gsum));
    float yb = ysum * 0.25f;
    float w = 1.0f - mv;
    int i4 = (gw << 5) + lane;
    float4 iv = ((const float4*)inp)[i4];
    float4 bv = ((const float4*)bias)[(p << 5) + lane];
    float4 o4;
    o4.x = sg * (iv.x + (yb + bv.x) * w);
    o4.y = sg * (iv.y + (yb + bv.y) * w);
    o4.z = sg * (iv.z + (yb + bv.z) * w);
    o4.w = sg * (iv.w + (yb + bv.w) * w);
    ((float4*)out)[i4] = o4;
}

// ---------------- launch ----------------
extern "C" void kernel_launch(void* const* d_in, const int* in_sizes, int n_in,
                              void* d_out, int out_size) {
    const float* inp   = (const float*)d_in[0];
    const float* mask  = (const float*)d_in[1];
    const float* bias  = (const float*)d_in[2];
    const float* convw = (const float*)d_in[3];
    float* out = (float*)d_out;

    kA<<<2049, 256>>>(inp, mask);
    kB_patches<<<(BB * PP) / 256, 256>>>();
    dim3 gD(GX, BB, SPLITS);
    kD_attn<<<gD, 128>>>();
    kF_final<<<(BB * PP) / 8, 256>>>(inp, mask, bias, convw, out);
}

// round 8
// speedup vs baseline: 1.5801x; 1.0317x over previous
#include <cuda_runtime.h>
#include <math.h>

#define BB 4
#define HH 64
#define WW 64
#define CC 128
#define PP 4096
#define SPLITS 12
#define GX 16
#define ROWS_PB 256
#define LOG2E 1.44269504088896340736f

typedef unsigned long long ull;

// ---------------- static scratch ----------------
__device__ float g_x[BB * PP * 2];          // per-pixel (mean, max)
__device__ float g_xfq[BB * PP * 20];       // queries pre-scaled by LOG2E, 18+2 pad
__device__ float g_M[BB * PP];              // M2 = patch L2 norm * LOG2E
__device__ float g_wn[BB * PP * 20];        // compacted normalized keys, 18+2 pad
__device__ float g_xfe[BB * PP * 12];       // compacted taps [t0..t8, 1.0, 0, 0]
__device__ float g_sig[BB * PP];            // sigmoid(gate conv) - computed in kB
__device__ int   g_vrank[PP];               // pixel -> compacted key index (or -1)
__device__ int   g_need[PP];
__device__ int   g_counts[2];               // [0]=n_valid, [1]=n_need
__device__ ull   g_pa[(size_t)BB * SPLITS * PP * 5];  // packed split partials (9 taps + l)
__device__ float g_tmp9[BB * PP * 9];
__device__ int   g_cnt[BB * GX];            // split arrival counters (self-resetting)

// ---- packed f32x2 helpers ----
__device__ __forceinline__ ull pk2(float lo, float hi) {
    ull r; asm("mov.b64 %0, {%1, %2};" : "=l"(r) : "f"(lo), "f"(hi)); return r;
}
__device__ __forceinline__ void upk(ull v, float& lo, float& hi) {
    asm("mov.b64 {%0, %1}, %2;" : "=f"(lo), "=f"(hi) : "l"(v));
}
__device__ __forceinline__ ull f2fma(ull a, ull b, ull c) {
    ull d; asm("fma.rn.f32x2 %0, %1, %2, %3;" : "=l"(d) : "l"(a), "l"(b), "l"(c)); return d;
}
__device__ __forceinline__ ull f2mul(ull a, ull b) {
    ull d; asm("mul.rn.f32x2 %0, %1, %2;" : "=l"(d) : "l"(a), "l"(b)); return d;
}
__device__ __forceinline__ ull f2add(ull a, ull b) {
    ull d; asm("add.rn.f32x2 %0, %1, %2;" : "=l"(d) : "l"(a), "l"(b)); return d;
}
__device__ __forceinline__ float ex2f(float x) {
    float r; asm("ex2.approx.f32 %0, %1;" : "=f"(r) : "f"(x)); return r;
}

// ---------------- KA: mean/max (blocks 0..2047) + compaction+vrank (block 2048) ----------------
__global__ void kA(const float* __restrict__ inp, const float* __restrict__ mask) {
    __shared__ int wv[8], wn_[8];
    if (blockIdx.x == 2048) {
        int t = threadIdx.x;
        int lane = t & 31, wid = t >> 5;
        unsigned fv = 0, fn = 0;
        int cv = 0, cn = 0;
        int base_p = t * 16;
        for (int i = 0; i < 16; i++) {
            int p = base_p + i, y = p >> 6, x = p & 63;
            int allone = 1, anyz = 0;
            #pragma unroll
            for (int dy = -1; dy <= 1; dy++)
                #pragma unroll
                for (int dx = -1; dx <= 1; dx++) {
                    int yy = y + dy, xx = x + dx;
                    if (yy < 0 || yy >= HH || xx < 0 || xx >= WW) {
                        allone = 0;
                    } else {
                        float mv = mask[(yy << 6) + xx];
                        if (mv < 0.5f) { allone = 0; anyz = 1; }
                    }
                }
            if (allone) { fv |= (1u << i); cv++; }
            if (anyz)   { fn |= (1u << i); cn++; }
        }
        int iv = cv, inn = cn;
        #pragma unroll
        for (int o = 1; o < 32; o <<= 1) {
            int a = __shfl_up_sync(0xffffffffu, iv, o);
            int b = __shfl_up_sync(0xffffffffu, inn, o);
            if (lane >= o) { iv += a; inn += b; }
        }
        if (lane == 31) { wv[wid] = iv; wn_[wid] = inn; }
        __syncthreads();
        int bv = 0, bn = 0;
        for (int i = 0; i < wid; i++) { bv += wv[i]; bn += wn_[i]; }
        int offv = bv + iv - cv;
        int offn = bn + inn - cn;
        for (int i = 0; i < 16; i++) {
            int p = base_p + i;
            if (fv & (1u << i)) g_vrank[p] = offv++;
            else                g_vrank[p] = -1;
            if (fn & (1u << i)) g_need[offn++] = p;
        }
        if (t == 255) { g_counts[0] = bv + iv; g_counts[1] = bn + inn; }
        return;
    }
    int warp = blockIdx.x * 8 + (threadIdx.x >> 5);
    int lane = threadIdx.x & 31;
    const float4* base = (const float4*)(inp + (size_t)warp * CC);
    float4 v = base[lane];
    float s = (v.x + v.y) + (v.z + v.w);
    float m = fmaxf(fmaxf(v.x, v.y), fmaxf(v.z, v.w));
    #pragma unroll
    for (int o = 16; o; o >>= 1) {
        s += __shfl_xor_sync(0xffffffffu, s, o);
        m = fmaxf(m, __shfl_xor_sync(0xffffffffu, m, o));
    }
    if (lane == 0) {
        g_x[warp * 2 + 0] = s * (1.0f / 128.0f);
        g_x[warp * 2 + 1] = m;
    }
}

// ---------------- KB: patch vectors + norms + compacted keys/values + gate conv ----------------
__global__ void kB_patches(const float* __restrict__ convw) {
    int idx = blockIdx.x * blockDim.x + threadIdx.x;   // BB*PP
    if (idx >= BB * PP) return;
    int p = idx & 4095, y = p >> 6, x = p & 63;
    int b = idx >> 12;
    float v[18];
    float ss = 0.f;
    int j = 0;
    #pragma unroll
    for (int kh = 0; kh < 3; kh++)
        #pragma unroll
        for (int kw = 0; kw < 3; kw++) {
            int yy = y + kh - 1, xx = x + kw - 1;
            float a = 0.f, c1 = 0.f;
            if (yy >= 0 && yy < HH && xx >= 0 && xx < WW) {
                int q = (b << 12) + (yy << 6) + xx;
                a  = g_x[q * 2 + 0];
                c1 = g_x[q * 2 + 1];
            }
            v[j] = a; v[j + 1] = c1;
            ss += a * a + c1 * c1;
            j += 2;
        }
    float Mn = sqrtf(ss);
    // query: pre-scaled by LOG2E
    float* dst = g_xfq + (size_t)idx * 20;
    #pragma unroll
    for (int i = 0; i < 18; i++) dst[i] = v[i] * LOG2E;
    dst[18] = 0.f; dst[19] = 0.f;
    g_M[idx] = Mn * LOG2E;
    // key/value if this pixel is a fully-valid patch
    int vr = g_vrank[p];
    if (vr >= 0) {
        float rn = 1.f / fmaxf(Mn, 1e-4f);
        float* dw = g_wn + (size_t)((b << 12) + vr) * 20;
        #pragma unroll
        for (int i = 0; i < 18; i++) dw[i] = v[i] * rn;
        dw[18] = 0.f; dw[19] = 0.f;
        float* de = g_xfe + (size_t)((b << 12) + vr) * 12;
        #pragma unroll
        for (int k = 0; k < 9; k++) de[k] = v[2 * k];
        de[9] = 1.0f;          // synthetic tap: accumulates the softmax denominator
        de[10] = 0.f; de[11] = 0.f;
    }
    // 7x7x2 gate conv + sigmoid (independent of attention)
    float g = 0.f;
    #pragma unroll
    for (int u = 0; u < 7; u++) {
        int yy = y + u - 3;
        if (yy < 0 || yy >= HH) continue;
        #pragma unroll
        for (int vv = 0; vv < 7; vv++) {
            int xx = x + vv - 3;
            if (xx < 0 || xx >= WW) continue;
            int q = (b << 12) + (yy << 6) + xx;
            g += g_x[q * 2 + 0] * __ldg(convw + (u * 7 + vv) * 2 + 0)
               + g_x[q * 2 + 1] * __ldg(convw + (u * 7 + vv) * 2 + 1);
        }
    }
    g_sig[idx] = 1.f / (1.f + __expf(-g));
}

// ---------------- KD: fused attention (f32x2, 2 rows/thread, shared key LDS) ----------------
__global__ void __launch_bounds__(128, 4) kD_attn() {
    __shared__ ulonglong2 swn[128 * 5];  // key dim-pairs
    __shared__ ulonglong2 sxe[128 * 3];  // tap pairs (t0,t1)..(t8,1.0)
    __shared__ int s_win;
    int nneed = g_counts[1];
    int x = blockIdx.x, b = blockIdx.y, s = blockIdx.z;
    if (x * ROWS_PB >= nneed) return;
    int nvalid = g_counts[0];
    int chunk = (nvalid + SPLITS - 1) / SPLITS;
    int v0 = s * chunk;
    int v1 = min(v0 + chunk, nvalid);
    int t = threadIdx.x;
    int r0 = x * ROWS_PB + t;
    int r1 = r0 + 128;
    bool act0 = r0 < nneed, act1 = r1 < nneed;

    ull qA[9], qB[9];
    float M2A, M2B;
    {
        int n = g_need[r0];
        const ulonglong2* qp = (const ulonglong2*)(g_xfq + (size_t)((b << 12) + n) * 20);
        ulonglong2 a_ = qp[0], b_ = qp[1], c_ = qp[2], d_ = qp[3], e_ = qp[4];
        qA[0] = a_.x; qA[1] = a_.y; qA[2] = b_.x; qA[3] = b_.y; qA[4] = c_.x;
        qA[5] = c_.y; qA[6] = d_.x; qA[7] = d_.y; qA[8] = e_.x;
        M2A = g_M[(b << 12) + n];
    }
    {
        int n = g_need[r1];
        const ulonglong2* qp = (const ulonglong2*)(g_xfq + (size_t)((b << 12) + n) * 20);
        ulonglong2 a_ = qp[0], b_ = qp[1], c_ = qp[2], d_ = qp[3], e_ = qp[4];
        qB[0] = a_.x; qB[1] = a_.y; qB[2] = b_.x; qB[3] = b_.y; qB[4] = c_.x;
        qB[5] = c_.y; qB[6] = d_.x; qB[7] = d_.y; qB[8] = e_.x;
        M2B = g_M[(b << 12) + n];
    }
    ull z = pk2(0.f, 0.f);
    ull aA0 = z, aA1 = z, aA2 = z, aA3 = z, aA4 = z;
    ull aB0 = z, aB1 = z, aB2 = z, aB3 = z, aB4 = z;

    for (int base = v0; base < v1; base += 128) {
        int cnt = min(128, v1 - base);
        __syncthreads();
        if (t < cnt) {
            const ulonglong2* srcw = (const ulonglong2*)(g_wn + (size_t)((b << 12) + base + t) * 20);
            #pragma unroll
            for (int w = 0; w < 5; w++) swn[t * 5 + w] = srcw[w];
            const ulonglong2* srcx = (const ulonglong2*)(g_xfe + (size_t)((b << 12) + base + t) * 12);
            #pragma unroll
            for (int w = 0; w < 3; w++) sxe[t * 3 + w] = srcx[w];
        }
        __syncthreads();
        for (int j = 0; j < cnt; j++) {
            ulonglong2 wa = swn[j * 5], wb = swn[j * 5 + 1], wc = swn[j * 5 + 2], wd = swn[j * 5 + 3];
            ull w8 = swn[j * 5 + 4].x;
            // row A: two independent chains
            ull m0 = f2mul(qA[0], wa.x);
            ull m1 = f2mul(qA[1], wa.y);
            m0 = f2fma(qA[2], wb.x, m0);
            m1 = f2fma(qA[3], wb.y, m1);
            m0 = f2fma(qA[4], wc.x, m0);
            m1 = f2fma(qA[5], wc.y, m1);
            m0 = f2fma(qA[6], wd.x, m0);
            m1 = f2fma(qA[7], wd.y, m1);
            m0 = f2fma(qA[8], w8, m0);
            // row B
            ull n0 = f2mul(qB[0], wa.x);
            ull n1 = f2mul(qB[1], wa.y);
            n0 = f2fma(qB[2], wb.x, n0);
            n1 = f2fma(qB[3], wb.y, n1);
            n0 = f2fma(qB[4], wc.x, n0);
            n1 = f2fma(qB[5], wc.y, n1);
            n0 = f2fma(qB[6], wd.x, n0);
            n1 = f2fma(qB[7], wd.y, n1);
            n0 = f2fma(qB[8], w8, n0);
            ull sa = f2add(m0, m1);
            ull sb = f2add(n0, n1);
            float alo, ahi, blo, bhi;
            upk(sa, alo, ahi);
            upk(sb, blo, bhi);
            float eA = ex2f((alo + ahi) - M2A);   // score <= M always (||wn||<=1)
            float eB = ex2f((blo + bhi) - M2B);
            ull eeA = pk2(eA, eA);
            ull eeB = pk2(eB, eB);
            ulonglong2 xa = sxe[j * 3], xb = sxe[j * 3 + 1], xc = sxe[j * 3 + 2];
            aA0 = f2fma(eeA, xa.x, aA0);  aB0 = f2fma(eeB, xa.x, aB0);
            aA1 = f2fma(eeA, xa.y, aA1);  aB1 = f2fma(eeB, xa.y, aB1);
            aA2 = f2fma(eeA, xb.x, aA2);  aB2 = f2fma(eeB, xb.x, aB2);
            aA3 = f2fma(eeA, xb.y, aA3);  aB3 = f2fma(eeB, xb.y, aB3);
            aA4 = f2fma(eeA, xc.x, aA4);  aB4 = f2fma(eeB, xc.x, aB4);  // (t8,1.0)->(acc8,l)
        }
    }
    if (act0) {
        ull* pa = g_pa + ((size_t)((b * SPLITS + s) << 12) + r0) * 5;
        pa[0] = aA0; pa[1] = aA1; pa[2] = aA2; pa[3] = aA3; pa[4] = aA4;
    }
    if (act1) {
        ull* pa = g_pa + ((size_t)((b * SPLITS + s) << 12) + r1) * 5;
        pa[0] = aB0; pa[1] = aB1; pa[2] = aB2; pa[3] = aB3; pa[4] = aB4;
    }
    // split-arrival; last block of this (b,x) group reduces (fixed s order => deterministic)
    __syncthreads();
    if (t == 0) {
        __threadfence();
        int old = atomicAdd(&g_cnt[b * GX + x], 1);
        s_win = (old == SPLITS - 1) ? 1 : 0;
        if (s_win) g_cnt[b * GX + x] = 0;        // reset for next graph replay
    }
    __syncthreads();
    if (s_win) {
        #pragma unroll
        for (int rr = 0; rr < 2; rr++) {
            int r = (rr == 0) ? r0 : r1;
            bool act = (rr == 0) ? act0 : act1;
            if (!act) continue;
            int n = g_need[r];
            float M2v = g_M[(b << 12) + n];
            ull c0 = z, c1 = z, c2 = z, c3 = z;
            ull c4 = pk2(0.f, (float)(PP - nvalid) * ex2f(-M2v));  // masked keys' denominator
            #pragma unroll
            for (int ss2 = 0; ss2 < SPLITS; ss2++) {
                const ull* pa = g_pa + ((size_t)((b * SPLITS + ss2) << 12) + r) * 5;
                c0 = f2add(c0, pa[0]);
                c1 = f2add(c1, pa[1]);
                c2 = f2add(c2, pa[2]);
                c3 = f2add(c3, pa[3]);
                c4 = f2add(c4, pa[4]);
            }
            float f[10];
            upk(c0, f[0], f[1]);
            upk(c1, f[2], f[3]);
            upk(c2, f[4], f[5]);
            upk(c3, f[6], f[7]);
            upk(c4, f[8], f[9]);
            float rl = 1.f / f[9];
            float* dst = g_tmp9 + (size_t)((b << 12) + n) * 9;
            #pragma unroll
            for (int k = 0; k < 9; k++) dst[k] = f[k] * rl;
        }
    }
}

// ---------------- KF: transpose-conv gather + final elementwise (gate conv precomputed) ----------------
__global__ void kF_final(const float* __restrict__ inp, const float* __restrict__ mask,
                         const float* __restrict__ bias, float* __restrict__ out) {
    int gw = blockIdx.x * 8 + (threadIdx.x >> 5);
    int lane = threadIdx.x & 31;
    int b = gw >> 12, p = gw & 4095, y = p >> 6, x = p & 63;
    float mv = mask[p];
    float ysum = 0.f;
    if (mv < 0.5f && lane < 9) {
        int kh = lane / 3, kw = lane % 3;
        int ny = y - (kh - 1), nx = x - (kw - 1);
        if (ny >= 0 && ny < HH && nx >= 0 && nx < WW)
            ysum = g_tmp9[(size_t)((b << 12) + (ny << 6) + nx) * 9 + lane];
    }
    #pragma unroll
    for (int o = 16; o; o >>= 1)
        ysum += __shfl_xor_sync(0xffffffffu, ysum, o);
    float sg = g_sig[gw];
    float yb = ysum * 0.25f;
    float w = 1.0f - mv;
    int i4 = (gw << 5) + lane;
    float4 iv = ((const float4*)inp)[i4];
    float4 bv = ((const float4*)bias)[(p << 5) + lane];
    float4 o4;
    o4.x = sg * (iv.x + (yb + bv.x) * w);
    o4.y = sg * (iv.y + (yb + bv.y) * w);
    o4.z = sg * (iv.z + (yb + bv.z) * w);
    o4.w = sg * (iv.w + (yb + bv.w) * w);
    ((float4*)out)[i4] = o4;
}

// ---------------- launch ----------------
extern "C" void kernel_launch(void* const* d_in, const int* in_sizes, int n_in,
                              void* d_out, int out_size) {
    const float* inp   = (const float*)d_in[0];
    const float* mask  = (const float*)d_in[1];
    const float* bias  = (const float*)d_in[2];
    const float* convw = (const float*)d_in[3];
    float* out = (float*)d_out;

    kA<<<2049, 256>>>(inp, mask);
    kB_patches<<<(BB * PP) / 256, 256>>>(convw);
    dim3 gD(GX, BB, SPLITS);
    kD_attn<<<gD, 128>>>();
    kF_final<<<(BB * PP) / 8, 256>>>(inp, mask, bias, out);
}